// round 5
// baseline (speedup 1.0000x reference)
#include <cuda_runtime.h>
#include <cuda_bf16.h>
#include <cstdint>

// Problem dims
#define BB   32
#define TT   2048
#define FF   64
#define HH   256
#define OUTD 64
#define ROWS (BB*TT)          // 65536
#define G3   (3*HH)           // 768

// ---------------- scratch (static device globals; no allocation) ----------------
__device__ float g_xn [ (size_t)ROWS * FF ];     // 16 MB  LayerNorm output
__device__ float g_xbR[ (size_t)ROWS * G3 ];     // 192 MB rearranged xb (reused by both GRUs)
__device__ float g_h1 [ (size_t)ROWS * HH ];     // 64 MB  GRU1 sequence output

// ---------------- helpers ----------------
__device__ __forceinline__ uint32_t smem_u32(const void* p) {
    uint32_t a;
    asm("{ .reg .u64 t; cvta.to.shared.u64 t, %1; cvt.u32.u64 %0, t; }" : "=r"(a) : "l"(p));
    return a;
}

// ---------------- LayerNorm: one warp per row of 64 ----------------
__global__ __launch_bounds__(256) void ln_kernel(
    const float* __restrict__ x, const float* __restrict__ gamma,
    const float* __restrict__ beta)
{
    int warp = (blockIdx.x * blockDim.x + threadIdx.x) >> 5;
    int lane = threadIdx.x & 31;
    if (warp >= ROWS) return;
    const float* row = x + (size_t)warp * FF;
    float2 v = *(const float2*)&row[lane * 2];
    float s = v.x + v.y;
    #pragma unroll
    for (int o = 16; o; o >>= 1) s += __shfl_xor_sync(~0u, s, o);
    float mu = s * (1.f / 64.f);
    float d0 = v.x - mu, d1 = v.y - mu;
    float q = d0 * d0 + d1 * d1;
    #pragma unroll
    for (int o = 16; o; o >>= 1) q += __shfl_xor_sync(~0u, q, o);
    float rs = rsqrtf(q * (1.f / 64.f) + 1e-3f);
    float2 g  = *(const float2*)&gamma[lane * 2];
    float2 bb = *(const float2*)&beta[lane * 2];
    float2 o2;
    o2.x = d0 * rs * g.x + bb.x;
    o2.y = d1 * rs * g.y + bb.y;
    *(float2*)&g_xn[(size_t)warp * FF + lane * 2] = o2;
}

// ---------------- projection GEMM: C[ROWS,768] = A[ROWS,K] @ W[K,768] + bias ----------------
// Output written into rearranged layout g_xbR[(b*4+rank)*T + t][cc],
//   where for global col g: gate=g/256, unit=g%256, rank=unit/64, cc=gate*64+(unit%64).
// Tile: 128 rows x 64 cols, 256 threads, each thread 8x4 outputs.
__global__ __launch_bounds__(256) void proj_kernel(
    int K, int use_h1, const float* __restrict__ W, const float* __restrict__ bias)
{
    __shared__ float As[128][68];  // [m][k], padded for alignment
    __shared__ float Ws[64][64];   // [k][n]

    const float* A = use_h1 ? g_h1 : g_xn;
    int cb = blockIdx.x * 64;
    int rb = blockIdx.y * 128;
    int tid  = threadIdx.x;
    int trow = tid >> 4;        // 0..15
    int tcol = tid & 15;        // 0..15

    float acc[8][4];
    #pragma unroll
    for (int i = 0; i < 8; i++)
        #pragma unroll
        for (int j = 0; j < 4; j++) acc[i][j] = 0.f;

    for (int kk = 0; kk < K; kk += 64) {
        // load A tile 128x64 (coalesced float4, no transpose)
        #pragma unroll
        for (int it = 0; it < 8; it++) {
            int r  = (tid >> 4) + it * 16;
            int kq = (tid & 15) * 4;
            float4 v = *(const float4*)&A[(size_t)(rb + r) * K + kk + kq];
            *(float4*)&As[r][kq] = v;
        }
        // load W tile 64x64
        #pragma unroll
        for (int it = 0; it < 4; it++) {
            int k  = (tid >> 4) + it * 16;
            int c4 = (tid & 15) * 4;
            float4 v = *(const float4*)&W[(size_t)(kk + k) * G3 + cb + c4];
            *(float4*)&Ws[k][c4] = v;
        }
        __syncthreads();
        #pragma unroll 16
        for (int k = 0; k < 64; k++) {
            float a[8], bv[4];
            #pragma unroll
            for (int i = 0; i < 8; i++) a[i] = As[trow * 8 + i][k];
            float4 b4 = *(const float4*)&Ws[k][tcol * 4];
            bv[0] = b4.x; bv[1] = b4.y; bv[2] = b4.z; bv[3] = b4.w;
            #pragma unroll
            for (int i = 0; i < 8; i++)
                #pragma unroll
                for (int j = 0; j < 4; j++) acc[i][j] += a[i] * bv[j];
        }
        __syncthreads();
    }

    // epilogue: bias + rearranged store
    #pragma unroll
    for (int i = 0; i < 8; i++) {
        int row = rb + trow * 8 + i;
        int b   = row >> 11;        // /2048
        int t   = row & 2047;
        #pragma unroll
        for (int j = 0; j < 4; j++) {
            int g    = cb + tcol * 4 + j;
            int gate = g >> 8;
            int unit = g & 255;
            int rnk  = unit >> 6;
            int cc   = gate * 64 + (unit & 63);
            size_t dst = (((size_t)(b * 4 + rnk)) * TT + t) * 192 + cc;
            g_xbR[dst] = acc[i][j] + bias[g];
        }
    }
}

// ---------------- GRU recurrence: cluster of 4 CTAs per batch ----------------
// CTA rank owns 64 h-units. 384 threads: q = tid/192 (k-chunk of 128), c = tid%192.
// Column c: gate = c/64 (z,r,h), unit = c%64, global col = gate*256 + rank*64 + unit.
// Thread keeps R[128] in registers. h in double-buffered SMEM, exchanged via DSMEM.
__global__ void __cluster_dims__(4, 1, 1) __launch_bounds__(384, 1)
gru_kernel(const float* __restrict__ rk, const float* __restrict__ rbias,
           const float* __restrict__ wd, const float* __restrict__ bd,
           float* __restrict__ out, int flags)  // flags bit0: write seq to g_h1, bit1: dense head
{
    __shared__ __align__(16) float h_sh[2][256];
    __shared__ float partial[2][192];

    int tid  = threadIdx.x;
    int rank = blockIdx.x;      // cluster rank (cluster dims (4,1,1))
    int b    = blockIdx.y;
    int q    = tid / 192;
    int c    = tid % 192;
    int gate = c >> 6;
    int u    = c & 63;
    int gcol = gate * 256 + rank * 64 + u;

    // load R slice into registers (one-time)
    float R[128];
    #pragma unroll
    for (int k = 0; k < 128; k++)
        R[k] = rk[(size_t)(q * 128 + k) * G3 + gcol];

    // zero initial h buffer
    for (int i = tid; i < 256; i += 384) h_sh[0][i] = 0.f;

    const float* xb = g_xbR + ((size_t)(b * 4 + rank)) * TT * 192;
    float rbz = 0.f, rbr = 0.f, rbh = 0.f, xz = 0.f, xr = 0.f, xh = 0.f;
    if (tid < 64) {
        rbz = rbias[rank * 64 + tid];
        rbr = rbias[256 + rank * 64 + tid];
        rbh = rbias[512 + rank * 64 + tid];
        xz = xb[tid]; xr = xb[64 + tid]; xh = xb[128 + tid];
    }
    __syncthreads();

    uint32_t h_base = smem_u32(&h_sh[0][0]);
    float* seqp = g_h1 + ((size_t)b * TT) * HH + rank * 64;
    int p = 0;

    for (int t = 0; t < TT; t++) {
        // ---- inner product: 128 MACs per thread, h from SMEM via float4 broadcast
        const float4* h4 = (const float4*)&h_sh[p][q * 128];
        float acc0 = 0.f, acc1 = 0.f;
        #pragma unroll
        for (int kk = 0; kk < 128; kk += 4) {
            float4 hv = h4[kk >> 2];
            acc0 += R[kk + 0] * hv.x; acc1 += R[kk + 1] * hv.y;
            acc0 += R[kk + 2] * hv.z; acc1 += R[kk + 3] * hv.w;
        }
        partial[q][c] = acc0 + acc1;
        __syncthreads();

        if (tid < 64) {
            // prefetch next step's xb first (latency hidden behind gates + cluster sync)
            float nxz = 0.f, nxr = 0.f, nxh = 0.f;
            if (t + 1 < TT) {
                const float* nxb = xb + (size_t)(t + 1) * 192;
                nxz = nxb[tid]; nxr = nxb[64 + tid]; nxh = nxb[128 + tid];
            }
            float rz = partial[0][tid]       + partial[1][tid]       + rbz;
            float rr = partial[0][64 + tid]  + partial[1][64 + tid]  + rbr;
            float rh = partial[0][128 + tid] + partial[1][128 + tid] + rbh;
            float z  = 1.f / (1.f + __expf(-(xz + rz)));
            float r  = 1.f / (1.f + __expf(-(xr + rr)));
            float hh = tanhf(xh + r * rh);
            float hp = h_sh[p][rank * 64 + tid];
            float hn = z * hp + (1.f - z) * hh;

            // broadcast h_new to all 4 cluster CTAs' other buffer
            uint32_t laddr = h_base + ((uint32_t)(((p ^ 1) * 256) + rank * 64 + tid) << 2);
            #pragma unroll
            for (int tg = 0; tg < 4; tg++) {
                uint32_t raddr;
                asm volatile("mapa.shared::cluster.u32 %0, %1, %2;"
                             : "=r"(raddr) : "r"(laddr), "r"(tg));
                asm volatile("st.shared::cluster.f32 [%0], %1;"
                             :: "r"(raddr), "f"(hn) : "memory");
            }
            if (flags & 1) seqp[(size_t)t * HH + tid] = hn;
            xz = nxz; xr = nxr; xh = nxh;
        }

        // one cluster barrier per step (release on arrive orders the DSMEM stores,
        // acquire on wait makes them visible before next step's reads)
        asm volatile("barrier.cluster.arrive.aligned;" ::: "memory");
        asm volatile("barrier.cluster.wait.aligned;"   ::: "memory");
        p ^= 1;
    }

    // dense head (GRU2 only): out[b] = h_last @ wd + bd, full h is in every CTA's SMEM
    if ((flags & 2) && rank == 0 && tid < 64) {
        float acc = bd[tid];
        #pragma unroll 8
        for (int k = 0; k < 256; k++) acc += h_sh[p][k] * wd[k * 64 + tid];
        out[b * 64 + tid] = acc;
    }
}

// ---------------- launch ----------------
extern "C" void kernel_launch(void* const* d_in, const int* in_sizes, int n_in,
                              void* d_out, int out_size)
{
    const float* x     = (const float*)d_in[0];
    const float* gamma = (const float*)d_in[1];
    const float* beta  = (const float*)d_in[2];
    const float* k1    = (const float*)d_in[3];
    const float* rk1   = (const float*)d_in[4];
    const float* b1    = (const float*)d_in[5];   // [2,768]
    const float* k2    = (const float*)d_in[6];
    const float* rk2   = (const float*)d_in[7];
    const float* b2    = (const float*)d_in[8];   // [2,768]
    const float* wd    = (const float*)d_in[9];
    const float* bd    = (const float*)d_in[10];
    float* out = (float*)d_out;

    (void)in_sizes; (void)n_in; (void)out_size;

    // 1) LayerNorm
    ln_kernel<<<ROWS / 8, 256>>>(x, gamma, beta);

    // 2) xb1 = xn @ k1 + b1[0]  (rearranged into g_xbR)
    proj_kernel<<<dim3(G3 / 64, ROWS / 128), 256>>>(FF, 0, k1, b1);

    // 3) GRU1: sequences -> g_h1
    gru_kernel<<<dim3(4, BB), 384>>>(rk1, b1 + G3, wd, bd, out, /*flags=*/1);

    // 4) xb2 = h1 @ k2 + b2[0]  (rearranged into g_xbR, reuse)
    proj_kernel<<<dim3(G3 / 64, ROWS / 128), 256>>>(HH, 1, k2, b2);

    // 5) GRU2 + dense head -> out
    gru_kernel<<<dim3(4, BB), 384>>>(rk2, b2 + G3, wd, bd, out, /*flags=*/2);
}

// round 6
// speedup vs baseline: 1.1808x; 1.1808x over previous
#include <cuda_runtime.h>
#include <cuda_bf16.h>
#include <cstdint>

// Problem dims
#define BB   32
#define TT   2048
#define FF   64
#define HH   256
#define OUTD 64
#define ROWS (BB*TT)          // 65536
#define G3   (3*HH)           // 768

// ---------------- scratch (static device globals; no allocation) ----------------
__device__ float g_xn [ (size_t)ROWS * FF ];     // 16 MB  LayerNorm output
__device__ float g_xbR[ (size_t)ROWS * G3 ];     // 192 MB rearranged xb (reused by both GRUs)
__device__ float g_h1 [ (size_t)ROWS * HH ];     // 64 MB  GRU1 sequence output

// ---------------- helpers ----------------
__device__ __forceinline__ uint32_t smem_u32(const void* p) {
    uint32_t a;
    asm("{ .reg .u64 t; cvta.to.shared.u64 t, %1; cvt.u32.u64 %0, t; }" : "=r"(a) : "l"(p));
    return a;
}
__device__ __forceinline__ unsigned long long pack2(float lo, float hi) {
    unsigned long long r;
    asm("mov.b64 %0, {%1, %2};" : "=l"(r) : "f"(lo), "f"(hi));
    return r;
}
__device__ __forceinline__ unsigned long long fma2(unsigned long long a, unsigned long long b,
                                                   unsigned long long c) {
    unsigned long long d;
    asm("fma.rn.f32x2 %0, %1, %2, %3;" : "=l"(d) : "l"(a), "l"(b), "l"(c));
    return d;
}
__device__ __forceinline__ unsigned long long add2(unsigned long long a, unsigned long long b) {
    unsigned long long d;
    asm("add.rn.f32x2 %0, %1, %2;" : "=l"(d) : "l"(a), "l"(b));
    return d;
}
__device__ __forceinline__ float hsum2(unsigned long long a) {
    float lo, hi;
    asm("mov.b64 {%0, %1}, %2;" : "=f"(lo), "=f"(hi) : "l"(a));
    return lo + hi;
}
__device__ __forceinline__ float tanh_fast(float x) {
    float y;
    asm("tanh.approx.f32 %0, %1;" : "=f"(y) : "f"(x));
    return y;
}
__device__ __forceinline__ float sigmoid_fast(float x) {
    return 0.5f * tanh_fast(0.5f * x) + 0.5f;
}
__device__ __forceinline__ void mbar_init(uint32_t a, uint32_t cnt) {
    asm volatile("mbarrier.init.shared.b64 [%0], %1;" :: "r"(a), "r"(cnt) : "memory");
}
__device__ __forceinline__ void mbar_expect(uint32_t a, uint32_t tx) {
    asm volatile("mbarrier.arrive.expect_tx.shared.b64 _, [%0], %1;" :: "r"(a), "r"(tx) : "memory");
}
__device__ __forceinline__ void mbar_wait(uint32_t addr, int phase) {
    asm volatile(
        "{\n\t.reg .pred P;\n\t"
        "WL_%=:\n\t"
        "mbarrier.try_wait.parity.acquire.cta.shared::cta.b64 P, [%0], %1, 0x989680;\n\t"
        "@P bra.uni WD_%=;\n\t"
        "bra.uni WL_%=;\n\t"
        "WD_%=:\n\t}"
        :: "r"(addr), "r"(phase) : "memory");
}
__device__ __forceinline__ uint32_t mapa_u32(uint32_t a, uint32_t rnk) {
    uint32_t r;
    asm("mapa.shared::cluster.u32 %0, %1, %2;" : "=r"(r) : "r"(a), "r"(rnk));
    return r;
}
__device__ __forceinline__ void st_async_f32(uint32_t addr, float v, uint32_t mbar) {
    asm volatile(
        "st.async.weak.shared::cluster.mbarrier::complete_tx::bytes.f32 [%0], %1, [%2];"
        :: "r"(addr), "f"(v), "r"(mbar) : "memory");
}

// ---------------- LayerNorm: one warp per row of 64 ----------------
__global__ __launch_bounds__(256) void ln_kernel(
    const float* __restrict__ x, const float* __restrict__ gamma,
    const float* __restrict__ beta)
{
    int warp = (blockIdx.x * blockDim.x + threadIdx.x) >> 5;
    int lane = threadIdx.x & 31;
    if (warp >= ROWS) return;
    const float* row = x + (size_t)warp * FF;
    float2 v = *(const float2*)&row[lane * 2];
    float s = v.x + v.y;
    #pragma unroll
    for (int o = 16; o; o >>= 1) s += __shfl_xor_sync(~0u, s, o);
    float mu = s * (1.f / 64.f);
    float d0 = v.x - mu, d1 = v.y - mu;
    float q = d0 * d0 + d1 * d1;
    #pragma unroll
    for (int o = 16; o; o >>= 1) q += __shfl_xor_sync(~0u, q, o);
    float rs = rsqrtf(q * (1.f / 64.f) + 1e-3f);
    float2 g  = *(const float2*)&gamma[lane * 2];
    float2 bb = *(const float2*)&beta[lane * 2];
    float2 o2;
    o2.x = d0 * rs * g.x + bb.x;
    o2.y = d1 * rs * g.y + bb.y;
    *(float2*)&g_xn[(size_t)warp * FF + lane * 2] = o2;
}

// ---------------- projection GEMM: C[ROWS,768] = A[ROWS,K] @ W[K,768] + bias ----------------
// A tile stored k-major in SMEM so m-pairs load packed (LDS.64); inner loop uses fma.rn.f32x2.
// Output written rearranged: g_xbR[(b*4+rank)*T + t][gate*64 + unit%64].
__global__ __launch_bounds__(256) void proj_kernel(
    int K, int use_h1, const float* __restrict__ W, const float* __restrict__ bias)
{
    __shared__ float As[64][132];  // [k][m], pad 4 -> 2-way STS conflicts only
    __shared__ float Ws[64][64];   // [k][n]

    const float* A = use_h1 ? g_h1 : g_xn;
    int cb = blockIdx.x * 64;
    int rb = blockIdx.y * 128;
    int tid  = threadIdx.x;
    int trow = tid >> 4;        // 0..15  (m group of 8)
    int tcol = tid & 15;        // 0..15  (n group of 4)

    unsigned long long acc[4][4];  // [m-pair][n], packed (row 2i, row 2i+1)
    #pragma unroll
    for (int i = 0; i < 4; i++)
        #pragma unroll
        for (int j = 0; j < 4; j++) acc[i][j] = 0ULL;

    for (int kk = 0; kk < K; kk += 64) {
        // load A tile 128 rows x 64 k, transposed into As[k][m]
        #pragma unroll
        for (int it = 0; it < 8; it++) {
            int r  = (tid >> 4) + it * 16;
            int kq = (tid & 15) * 4;
            float4 v = *(const float4*)&A[(size_t)(rb + r) * K + kk + kq];
            As[kq + 0][r] = v.x;
            As[kq + 1][r] = v.y;
            As[kq + 2][r] = v.z;
            As[kq + 3][r] = v.w;
        }
        // load W tile 64x64
        #pragma unroll
        for (int it = 0; it < 4; it++) {
            int k  = (tid >> 4) + it * 16;
            int c4 = (tid & 15) * 4;
            float4 v = *(const float4*)&W[(size_t)(kk + k) * G3 + cb + c4];
            *(float4*)&Ws[k][c4] = v;
        }
        __syncthreads();
        #pragma unroll 8
        for (int k = 0; k < 64; k++) {
            const unsigned long long* ap =
                (const unsigned long long*)&As[k][trow * 8];  // 4 packed m-pairs
            unsigned long long a0 = ap[0], a1 = ap[1], a2 = ap[2], a3 = ap[3];
            float4 b4 = *(const float4*)&Ws[k][tcol * 4];
            unsigned long long bb0 = pack2(b4.x, b4.x);
            unsigned long long bb1 = pack2(b4.y, b4.y);
            unsigned long long bb2 = pack2(b4.z, b4.z);
            unsigned long long bb3 = pack2(b4.w, b4.w);
            acc[0][0] = fma2(a0, bb0, acc[0][0]); acc[0][1] = fma2(a0, bb1, acc[0][1]);
            acc[0][2] = fma2(a0, bb2, acc[0][2]); acc[0][3] = fma2(a0, bb3, acc[0][3]);
            acc[1][0] = fma2(a1, bb0, acc[1][0]); acc[1][1] = fma2(a1, bb1, acc[1][1]);
            acc[1][2] = fma2(a1, bb2, acc[1][2]); acc[1][3] = fma2(a1, bb3, acc[1][3]);
            acc[2][0] = fma2(a2, bb0, acc[2][0]); acc[2][1] = fma2(a2, bb1, acc[2][1]);
            acc[2][2] = fma2(a2, bb2, acc[2][2]); acc[2][3] = fma2(a2, bb3, acc[2][3]);
            acc[3][0] = fma2(a3, bb0, acc[3][0]); acc[3][1] = fma2(a3, bb1, acc[3][1]);
            acc[3][2] = fma2(a3, bb2, acc[3][2]); acc[3][3] = fma2(a3, bb3, acc[3][3]);
        }
        __syncthreads();
    }

    // epilogue: bias + rearranged store
    #pragma unroll
    for (int i2 = 0; i2 < 4; i2++) {
        float lo, hi;
        #pragma unroll
        for (int j = 0; j < 4; j++) {
            asm("mov.b64 {%0, %1}, %2;" : "=f"(lo), "=f"(hi) : "l"(acc[i2][j]));
            int g    = cb + tcol * 4 + j;
            int gate = g >> 8;
            int unit = g & 255;
            int rnk  = unit >> 6;
            int cc   = gate * 64 + (unit & 63);
            float bv = bias[g];
            #pragma unroll
            for (int half = 0; half < 2; half++) {
                int row = rb + trow * 8 + 2 * i2 + half;
                int b   = row >> 11;
                int t   = row & 2047;
                size_t dst = (((size_t)(b * 4 + rnk)) * TT + t) * 192 + cc;
                g_xbR[dst] = (half ? hi : lo) + bv;
            }
        }
    }
}

// ---------------- GRU recurrence: cluster of 4 CTAs per batch ----------------
// 384 threads: q = tid/192 (k-half of 128), c = tid%192 (gate*64+unit).
// R slice in registers as packed f32x2; h double-buffered in SMEM; cross-CTA
// h exchange via st.async + mbarrier complete_tx (parity pair, no cluster barrier).
__global__ void __cluster_dims__(4, 1, 1) __launch_bounds__(384, 1)
gru_kernel(const float* __restrict__ rk, const float* __restrict__ rbias,
           const float* __restrict__ wd, const float* __restrict__ bd,
           float* __restrict__ out, int flags)  // bit0: write seq to g_h1, bit1: dense head
{
    __shared__ __align__(16) float h_sh[2][256];
    __shared__ float partial[2][192];
    __shared__ __align__(8) unsigned long long mbar[2];

    int tid  = threadIdx.x;
    int rank = blockIdx.x;      // cluster rank
    int b    = blockIdx.y;
    int q    = tid / 192;
    int c    = tid % 192;
    int gate = c >> 6;
    int u    = c & 63;
    int gcol = gate * 256 + rank * 64 + u;

    // load R slice into packed registers (one-time): R2[i] = (rk[2i], rk[2i+1]) down column gcol
    unsigned long long R2[64];
    #pragma unroll
    for (int i = 0; i < 64; i++) {
        float lo = rk[(size_t)(q * 128 + 2 * i)     * G3 + gcol];
        float hi = rk[(size_t)(q * 128 + 2 * i + 1) * G3 + gcol];
        R2[i] = pack2(lo, hi);
    }

    uint32_t mb0 = smem_u32(&mbar[0]);
    uint32_t mb1 = smem_u32(&mbar[1]);
    uint32_t hb  = smem_u32(&h_sh[0][0]);

    if (tid == 0) {
        mbar_init(mb0, 1);
        mbar_init(mb1, 1);
        mbar_expect(mb1, 1024);   // X_1 (delivered during step 0)
    }
    for (int i = tid; i < 256; i += 384) h_sh[0][i] = 0.f;  // h_0 = 0 in buf 0
    __syncthreads();
    asm volatile("barrier.cluster.arrive.aligned;" ::: "memory");
    asm volatile("barrier.cluster.wait.aligned;"   ::: "memory");

    const float* xb = g_xbR + ((size_t)(b * 4 + rank)) * TT * 192;
    float rbz = 0.f, rbr = 0.f, rbh = 0.f, xz = 0.f, xr = 0.f, xh = 0.f;
    uint32_t rmb[4], rhb[4];  // remote mbar[0] / h_sh base per target CTA (window-linear)
    if (tid < 64) {
        rbz = rbias[rank * 64 + tid];
        rbr = rbias[256 + rank * 64 + tid];
        rbh = rbias[512 + rank * 64 + tid];
        xz = xb[tid]; xr = xb[64 + tid]; xh = xb[128 + tid];
        #pragma unroll
        for (int tg = 0; tg < 4; tg++) {
            rmb[tg] = mapa_u32(mb0, tg);
            rhb[tg] = mapa_u32(hb, tg);
        }
    }

    float* seqp = g_h1 + ((size_t)b * TT) * HH + rank * 64;
    int ph0 = 0, ph1 = 0;

    for (int t = 0; t < TT; t++) {
        int k = t & 1;                       // h_t lives in buf[k], exchange X_t on mbar[k]
        if (t) {
            if (k) { mbar_wait(mb1, ph1); ph1 ^= 1; }
            else   { mbar_wait(mb0, ph0); ph0 ^= 1; }
        }
        if (tid == 0 && t + 2 <= TT)
            mbar_expect(k ? mb1 : mb0, 1024);   // X_{t+2} on same mbar

        // ---- inner product: 64 packed fma2 per thread
        const ulonglong2* h4 = (const ulonglong2*)&h_sh[k][q * 128];
        unsigned long long a0 = 0ULL, a1 = 0ULL, a2 = 0ULL, a3 = 0ULL;
        #pragma unroll
        for (int i = 0; i < 16; i++) {
            ulonglong2 hv1 = h4[2 * i];
            ulonglong2 hv2 = h4[2 * i + 1];
            a0 = fma2(R2[4 * i + 0], hv1.x, a0);
            a1 = fma2(R2[4 * i + 1], hv1.y, a1);
            a2 = fma2(R2[4 * i + 2], hv2.x, a2);
            a3 = fma2(R2[4 * i + 3], hv2.y, a3);
        }
        partial[q][c] = hsum2(add2(add2(a0, a1), add2(a2, a3)));
        __syncthreads();

        if (tid < 64) {
            // prefetch next step's xb (hidden behind gates + exchange)
            float nxz = 0.f, nxr = 0.f, nxh = 0.f;
            if (t + 1 < TT) {
                const float* nxb = xb + (size_t)(t + 1) * 192;
                nxz = nxb[tid]; nxr = nxb[64 + tid]; nxh = nxb[128 + tid];
            }
            float rz = partial[0][tid]       + partial[1][tid]       + rbz;
            float rr = partial[0][64 + tid]  + partial[1][64 + tid]  + rbr;
            float rh = partial[0][128 + tid] + partial[1][128 + tid] + rbh;
            float z  = sigmoid_fast(xz + rz);
            float r  = sigmoid_fast(xr + rr);
            float hh = tanh_fast(xh + r * rh);
            float hp = h_sh[k][rank * 64 + tid];
            float hn = z * hp + (1.f - z) * hh;

            if (flags & 1) seqp[(size_t)t * HH + tid] = hn;

            // h_{t+1} -> buf[k^1] + mbar[k^1] of all 4 CTAs, via async store + tx
            if ((flags & 2) || t + 1 < TT) {
                uint32_t boff = (uint32_t)(((k ^ 1) * 256 + rank * 64 + tid) << 2);
                uint32_t moff = (uint32_t)((k ^ 1) * 8);
                #pragma unroll
                for (int tg = 0; tg < 4; tg++)
                    st_async_f32(rhb[tg] + boff, hn, rmb[tg] + moff);
            }
            xz = nxz; xr = nxr; xh = nxh;
        }
        // no barrier here: the next mbar_wait provides the cross/intra-CTA sync
    }

    // dense head (GRU2): wait final exchange X_TT (on mbar[0], parity ph0), then out = h@wd+bd
    if (flags & 2) {
        mbar_wait(mb0, ph0);
        if (rank == 0 && tid < 64) {
            float acc = bd[tid];
            #pragma unroll 8
            for (int kk2 = 0; kk2 < 256; kk2++) acc += h_sh[0][kk2] * wd[kk2 * 64 + tid];
            out[b * 64 + tid] = acc;
        }
    }
}

// ---------------- launch ----------------
extern "C" void kernel_launch(void* const* d_in, const int* in_sizes, int n_in,
                              void* d_out, int out_size)
{
    const float* x     = (const float*)d_in[0];
    const float* gamma = (const float*)d_in[1];
    const float* beta  = (const float*)d_in[2];
    const float* k1    = (const float*)d_in[3];
    const float* rk1   = (const float*)d_in[4];
    const float* b1    = (const float*)d_in[5];   // [2,768]
    const float* k2    = (const float*)d_in[6];
    const float* rk2   = (const float*)d_in[7];
    const float* b2    = (const float*)d_in[8];   // [2,768]
    const float* wd    = (const float*)d_in[9];
    const float* bd    = (const float*)d_in[10];
    float* out = (float*)d_out;

    (void)in_sizes; (void)n_in; (void)out_size;

    ln_kernel<<<ROWS / 8, 256>>>(x, gamma, beta);
    proj_kernel<<<dim3(G3 / 64, ROWS / 128), 256>>>(FF, 0, k1, b1);
    gru_kernel<<<dim3(4, BB), 384>>>(rk1, b1 + G3, wd, bd, out, /*flags=*/1);
    proj_kernel<<<dim3(G3 / 64, ROWS / 128), 256>>>(HH, 1, k2, b2);
    gru_kernel<<<dim3(4, BB), 384>>>(rk2, b2 + G3, wd, bd, out, /*flags=*/2);
}